// round 1
// baseline (speedup 1.0000x reference)
#include <cuda_runtime.h>
#include <cstdint>

#define NODES 50000
#define EDGES 800000
#define HID   128
#define NLAYER 3

// ---------------- scratch (static device globals; no allocation) ----------------
__device__ float g_x   [NODES * HID];       // node state
__device__ float g_pq  [NODES * 2 * HID];   // [P | Q] per node (P has b1 folded in)
__device__ float g_H   [NODES * HID];       // segment_sum(relu_h)
__device__ float g_aggr[NODES * HID];       // aggregated message after W2
__device__ float g_t   [NODES * HID];       // update-MLP hidden
__device__ int   g_esrc[EDGES];
__device__ float g_eea [EDGES];
__device__ int   g_deg [NODES];
__device__ int   g_rowptr[NODES + 1];
__device__ int   g_cursor[NODES];
__device__ float g_invdeg[NODES];
__device__ float g_gate  [NODES];           // 1 if deg>0 else 0
__device__ float g_wcat  [HID * 2 * HID];   // repacked [W1a | W1b]  (128 x 256)
__device__ float g_bias2h[2 * HID];         // [b1 | 0]
__device__ float g_gvec  [HID];
__device__ int   g_is64;

// ---------------- edge-index width detection ----------------
__global__ void k_detect(const int* __restrict__ ei) {
    if (blockIdx.x == 0 && threadIdx.x == 0) {
        int z = 1;
        #pragma unroll
        for (int i = 1; i < 16; i += 2) if (ei[i] != 0) z = 0;
        g_is64 = z;
    }
}

__global__ void k_zero_deg(int N) {
    int i = blockIdx.x * blockDim.x + threadIdx.x;
    if (i < N) g_deg[i] = 0;
}

__global__ void k_count(const int* __restrict__ ei, int E) {
    int e = blockIdx.x * blockDim.x + threadIdx.x;
    if (e >= E) return;
    int is64 = g_is64;
    int dst = is64 ? ei[2 * E + 2 * e] : ei[E + e];
    atomicAdd(&g_deg[dst], 1);
}

// single-block inclusive scan over deg -> rowptr/cursor/invdeg/gate
__global__ void k_scan(int N) {
    __shared__ int s[1024];
    __shared__ int carry;
    int tid = threadIdx.x;
    if (tid == 0) carry = 0;
    __syncthreads();
    for (int base = 0; base < N; base += 1024) {
        int i = base + tid;
        int v = (i < N) ? g_deg[i] : 0;
        s[tid] = v;
        __syncthreads();
        for (int off = 1; off < 1024; off <<= 1) {
            int t = (tid >= off) ? s[tid - off] : 0;
            __syncthreads();
            s[tid] += t;
            __syncthreads();
        }
        int c = carry;
        if (i < N) {
            int excl = c + s[tid] - v;
            g_rowptr[i] = excl;
            g_cursor[i] = excl;
            g_invdeg[i] = 1.0f / fmaxf((float)v, 1.0f);
            g_gate[i]   = (v > 0) ? 1.0f : 0.0f;
        }
        __syncthreads();
        if (tid == 0) carry = c + s[1023];
        __syncthreads();
    }
    if (tid == 0) g_rowptr[N] = carry;
}

__global__ void k_scatter(const int* __restrict__ ei, const float* __restrict__ ea, int E) {
    int e = blockIdx.x * blockDim.x + threadIdx.x;
    if (e >= E) return;
    int is64 = g_is64;
    int src = is64 ? ei[2 * e]         : ei[e];
    int dst = is64 ? ei[2 * E + 2 * e] : ei[E + e];
    int pos = atomicAdd(&g_cursor[dst], 1);
    g_esrc[pos] = src;
    g_eea[pos]  = ea[e];
}

// ---------------- encoder: x = node_feat @ enc_W + enc_b ----------------
__global__ void k_encode(const float* __restrict__ nf, const float* __restrict__ W,
                         const float* __restrict__ b, int N) {
    int t = blockIdx.x * blockDim.x + threadIdx.x;
    if (t >= N * HID) return;
    int n = t >> 7, c = t & 127;
    float acc = b[c];
    #pragma unroll
    for (int k = 0; k < 5; k++) acc = fmaf(nf[n * 5 + k], W[k * HID + c], acc);
    g_x[t] = acc;
}

// ---------------- repack W1 -> [W1a | W1b], bias -> [b1 | 0] ----------------
__global__ void k_repack(const float* __restrict__ W1l, const float* __restrict__ b1l) {
    int t = blockIdx.x * blockDim.x + threadIdx.x;
    if (t < HID * 2 * HID) {
        int k = t >> 8, j = t & 255;
        g_wcat[t] = (j < 128) ? W1l[k * 128 + j] : W1l[(128 + k) * 128 + (j - 128)];
    }
    if (t < 256) g_bias2h[t] = (t < 128) ? b1l[t] : 0.0f;
}

// ---------------- generic fused fp32 GEMM ----------------
// C[M, NO] = epilogue( A1[M,128] @ B1[128,NO] (+ A2[M,128] @ B2[128,NO]) )
// Tile 64x128, 256 threads, 8x4 per-thread accumulators, K-chunk 32.
template<bool HAS_A2, bool RELU, bool SCALEBIAS, bool LN>
__global__ void __launch_bounds__(256) gemm_k(
    const float* __restrict__ A1, const float* __restrict__ A2,
    const float* __restrict__ B1, const float* __restrict__ B2,
    const float* __restrict__ bias,
    const float* __restrict__ rowscale, const float* __restrict__ rowgate,
    const float* __restrict__ lng, const float* __restrict__ lnb,
    float* __restrict__ C, int M, int NO)
{
    __shared__ float smem[64 * 128];          // 32 KB, reused as Cs for LN
    float* As = smem;                          // [32][64]
    float* Bs = smem + 32 * 64;                // [32][128]

    const int tid = threadIdx.x;
    const int tx = tid & 31;
    const int ty = tid >> 5;
    const int m0 = blockIdx.y * 64;
    const int colbase = blockIdx.x * 128;

    float acc[8][4];
    #pragma unroll
    for (int r = 0; r < 8; r++)
        #pragma unroll
        for (int c = 0; c < 4; c++) acc[r][c] = 0.0f;

    const int npass = HAS_A2 ? 2 : 1;
    for (int p = 0; p < npass; p++) {
        const float* A = (p == 0) ? A1 : A2;
        const float* B = (p == 0) ? B1 : B2;
        for (int k0 = 0; k0 < 128; k0 += 32) {
            // A chunk 64x32 -> As[k][m] (transposed)
            #pragma unroll
            for (int i = 0; i < 2; i++) {
                int f = tid + i * 256;        // 0..511
                int m = f >> 3;
                int f4 = f & 7;
                float4 a = make_float4(0.f, 0.f, 0.f, 0.f);
                if (m0 + m < M)
                    a = *(const float4*)&A[(size_t)(m0 + m) * 128 + k0 + f4 * 4];
                As[(f4 * 4 + 0) * 64 + m] = a.x;
                As[(f4 * 4 + 1) * 64 + m] = a.y;
                As[(f4 * 4 + 2) * 64 + m] = a.z;
                As[(f4 * 4 + 3) * 64 + m] = a.w;
            }
            // B chunk 32x128 (row stride = NO)
            #pragma unroll
            for (int i = 0; i < 4; i++) {
                int f = tid + i * 256;        // 0..1023
                int k = f >> 5;
                int c4 = f & 31;
                *(float4*)&Bs[k * 128 + c4 * 4] =
                    *(const float4*)&B[(size_t)(k0 + k) * NO + colbase + c4 * 4];
            }
            __syncthreads();
            #pragma unroll
            for (int k = 0; k < 32; k++) {
                float4 a0 = *(const float4*)&As[k * 64 + ty * 8];
                float4 a1 = *(const float4*)&As[k * 64 + ty * 8 + 4];
                float4 b  = *(const float4*)&Bs[k * 128 + tx * 4];
                float av[8] = {a0.x, a0.y, a0.z, a0.w, a1.x, a1.y, a1.z, a1.w};
                float bv[4] = {b.x, b.y, b.z, b.w};
                #pragma unroll
                for (int r = 0; r < 8; r++)
                    #pragma unroll
                    for (int c = 0; c < 4; c++)
                        acc[r][c] = fmaf(av[r], bv[c], acc[r][c]);
            }
            __syncthreads();
        }
    }

    if (LN) {
        // bias add, stash full rows to smem, then per-row LayerNorm + relu
        float* Cs = smem;
        #pragma unroll
        for (int r = 0; r < 8; r++) {
            int row = ty * 8 + r;
            float4 v;
            v.x = acc[r][0] + bias[tx * 4 + 0];
            v.y = acc[r][1] + bias[tx * 4 + 1];
            v.z = acc[r][2] + bias[tx * 4 + 2];
            v.w = acc[r][3] + bias[tx * 4 + 3];
            *(float4*)&Cs[row * 128 + tx * 4] = v;
        }
        __syncthreads();
        int lane = tx;
        #pragma unroll
        for (int rr = 0; rr < 8; rr++) {
            int row = ty * 8 + rr;
            int m = m0 + row;
            float4 v = *(const float4*)&Cs[row * 128 + lane * 4];
            float s  = v.x + v.y + v.z + v.w;
            float s2 = v.x * v.x + v.y * v.y + v.z * v.z + v.w * v.w;
            #pragma unroll
            for (int o = 16; o > 0; o >>= 1) {
                s  += __shfl_xor_sync(0xffffffffu, s,  o);
                s2 += __shfl_xor_sync(0xffffffffu, s2, o);
            }
            float mu  = s * (1.0f / 128.0f);
            float var = s2 * (1.0f / 128.0f) - mu * mu;
            float rs  = rsqrtf(var + 1e-5f);
            if (m < M) {
                float4 gg = *(const float4*)&lng[lane * 4];
                float4 bb = *(const float4*)&lnb[lane * 4];
                float4 o;
                o.x = fmaxf((v.x - mu) * rs * gg.x + bb.x, 0.0f);
                o.y = fmaxf((v.y - mu) * rs * gg.y + bb.y, 0.0f);
                o.z = fmaxf((v.z - mu) * rs * gg.z + bb.z, 0.0f);
                o.w = fmaxf((v.w - mu) * rs * gg.w + bb.w, 0.0f);
                *(float4*)&C[(size_t)m * 128 + lane * 4] = o;
            }
        }
    } else {
        #pragma unroll
        for (int r = 0; r < 8; r++) {
            int m = m0 + ty * 8 + r;
            if (m >= M) continue;
            float vals[4];
            float rsc = 1.0f, gt = 1.0f;
            if (SCALEBIAS) { rsc = rowscale[m]; gt = rowgate[m]; }
            #pragma unroll
            for (int c = 0; c < 4; c++) {
                float bcol = bias[colbase + tx * 4 + c];
                float v = SCALEBIAS ? (acc[r][c] * rsc + gt * bcol) : (acc[r][c] + bcol);
                if (RELU) v = fmaxf(v, 0.0f);
                vals[c] = v;
            }
            float4 o = make_float4(vals[0], vals[1], vals[2], vals[3]);
            *(float4*)&C[(size_t)m * NO + colbase + tx * 4] = o;
        }
    }
}

// ---------------- edge aggregation: warp per node, no float atomics ----------------
// H[n] = sum_{edges (s->n)} relu( P[n] + Q[s] + ea * w1c )   (P has b1 folded in)
__global__ void __launch_bounds__(256) k_aggr(const float* __restrict__ w1c, int N) {
    int warp = (blockIdx.x * blockDim.x + threadIdx.x) >> 5;
    int lane = threadIdx.x & 31;
    if (warp >= N) return;
    int node = warp;
    float4 p = *(const float4*)&g_pq[(size_t)node * 256 + lane * 4];
    float4 w = *(const float4*)&w1c[lane * 4];
    float4 acc = make_float4(0.f, 0.f, 0.f, 0.f);
    int s0 = g_rowptr[node], s1 = g_rowptr[node + 1];
    for (int j = s0; j < s1; j++) {
        int src  = g_esrc[j];
        float ea = g_eea[j];
        float4 q = *(const float4*)&g_pq[(size_t)src * 256 + 128 + lane * 4];
        acc.x += fmaxf(fmaf(ea, w.x, p.x + q.x), 0.0f);
        acc.y += fmaxf(fmaf(ea, w.y, p.y + q.y), 0.0f);
        acc.z += fmaxf(fmaf(ea, w.z, p.z + q.z), 0.0f);
        acc.w += fmaxf(fmaf(ea, w.w, p.w + q.w), 0.0f);
    }
    *(float4*)&g_H[(size_t)node * 128 + lane * 4] = acc;
}

// ---------------- readout ----------------
__global__ void k_zero_gvec() { if (threadIdx.x < 128) g_gvec[threadIdx.x] = 0.0f; }

__global__ void k_mean(int N) {
    int c = threadIdx.x;   // 128 threads
    int rows_per = (N + gridDim.x - 1) / gridDim.x;
    int r0 = blockIdx.x * rows_per;
    int r1 = min(r0 + rows_per, N);
    float s = 0.0f;
    for (int r = r0; r < r1; r++) s += g_x[(size_t)r * 128 + c];
    atomicAdd(&g_gvec[c], s);
}

__global__ void k_out(const float* __restrict__ W1, const float* __restrict__ b1,
                      const float* __restrict__ W2, const float* __restrict__ b2,
                      float* __restrict__ out, float invN) {
    __shared__ float gs[128];
    __shared__ float hs[128];
    int c = threadIdx.x;
    gs[c] = g_gvec[c] * invN;
    __syncthreads();
    float a = b1[c];
    #pragma unroll 8
    for (int k = 0; k < 128; k++) a = fmaf(gs[k], W1[k * 128 + c], a);
    hs[c] = fmaxf(a, 0.0f);
    __syncthreads();
    float o = b2[c];
    #pragma unroll 8
    for (int k = 0; k < 128; k++) o = fmaf(hs[k], W2[k * 128 + c], o);
    out[c] = o;
}

// ---------------- launch ----------------
extern "C" void kernel_launch(void* const* d_in, const int* in_sizes, int n_in,
                              void* d_out, int out_size) {
    const float* node_feat = (const float*)d_in[0];
    const float* edge_attr = (const float*)d_in[1];
    const float* enc_W  = (const float*)d_in[2];
    const float* enc_b  = (const float*)d_in[3];
    const float* mlp_W1 = (const float*)d_in[4];
    const float* mlp_b1 = (const float*)d_in[5];
    const float* mlp_W2 = (const float*)d_in[6];
    const float* mlp_b2 = (const float*)d_in[7];
    const float* upd_W1 = (const float*)d_in[8];
    const float* upd_b1 = (const float*)d_in[9];
    const float* upd_W2 = (const float*)d_in[10];
    const float* upd_b2 = (const float*)d_in[11];
    const float* ln_g   = (const float*)d_in[12];
    const float* ln_b   = (const float*)d_in[13];
    const float* out_W1 = (const float*)d_in[14];
    const float* out_b1 = (const float*)d_in[15];
    const float* out_W2 = (const float*)d_in[16];
    const float* out_b2 = (const float*)d_in[17];
    const int*   ei     = (const int*)d_in[18];

    const int N = NODES;
    const int E = EDGES;

    // device-global scratch addresses (query only; no allocation)
    float *px, *ppq, *pH, *paggr, *pt, *pwcat, *pbias, *pinv, *pgate;
    cudaGetSymbolAddress((void**)&px,    g_x);
    cudaGetSymbolAddress((void**)&ppq,   g_pq);
    cudaGetSymbolAddress((void**)&pH,    g_H);
    cudaGetSymbolAddress((void**)&paggr, g_aggr);
    cudaGetSymbolAddress((void**)&pt,    g_t);
    cudaGetSymbolAddress((void**)&pwcat, g_wcat);
    cudaGetSymbolAddress((void**)&pbias, g_bias2h);
    cudaGetSymbolAddress((void**)&pinv,  g_invdeg);
    cudaGetSymbolAddress((void**)&pgate, g_gate);

    // CSR build (int atomics only; deterministic sums downstream)
    k_detect<<<1, 32>>>(ei);
    k_zero_deg<<<(N + 255) / 256, 256>>>(N);
    k_count<<<(E + 255) / 256, 256>>>(ei, E);
    k_scan<<<1, 1024>>>(N);
    k_scatter<<<(E + 255) / 256, 256>>>(ei, edge_attr, E);

    // encoder
    k_encode<<<(N * HID + 255) / 256, 256>>>(node_feat, enc_W, enc_b, N);

    dim3 g2(2, (N + 63) / 64);
    dim3 g1(1, (N + 63) / 64);

    for (int l = 0; l < NLAYER; l++) {
        const float* W1l = mlp_W1 + (size_t)l * 257 * 128;
        k_repack<<<128, 256>>>(W1l, mlp_b1 + l * 128);

        // [P|Q] = x @ [W1a|W1b] + [b1|0]
        gemm_k<false, false, false, false><<<g2, 256>>>(
            px, nullptr, pwcat, nullptr, pbias,
            nullptr, nullptr, nullptr, nullptr, ppq, N, 256);

        // H[n] = sum relu(P[n]+Q[src]+ea*w1c)
        k_aggr<<<(N + 7) / 8, 256>>>(W1l + 256 * 128, N);

        // aggr = (H @ W2) * inv_deg + gate * b2
        gemm_k<false, false, true, false><<<g1, 256>>>(
            pH, nullptr, mlp_W2 + (size_t)l * 128 * 128, nullptr, mlp_b2 + l * 128,
            pinv, pgate, nullptr, nullptr, paggr, N, 128);

        // t = relu(x @ U1a + aggr @ U1b + b1)
        gemm_k<true, true, false, false><<<g1, 256>>>(
            px, paggr,
            upd_W1 + (size_t)l * 256 * 128, upd_W1 + (size_t)l * 256 * 128 + 128 * 128,
            upd_b1 + l * 128,
            nullptr, nullptr, nullptr, nullptr, pt, N, 128);

        // x = relu(LN(t @ U2 + b2))
        gemm_k<false, false, false, true><<<g1, 256>>>(
            pt, nullptr, upd_W2 + (size_t)l * 128 * 128, nullptr, upd_b2 + l * 128,
            nullptr, nullptr, ln_g + l * 128, ln_b + l * 128, px, N, 128);
    }

    // readout
    k_zero_gvec<<<1, 128>>>();
    k_mean<<<400, 128>>>(N);
    k_out<<<1, 128>>>(out_W1, out_b1, out_W2, out_b2, (float*)d_out, 1.0f / (float)N);
}

// round 3
// speedup vs baseline: 2.0489x; 2.0489x over previous
#include <cuda_runtime.h>
#include <cstdint>

#define NODES 50000
#define EDGES 800000
#define HID   128
#define NLAYER 3

// ---------------- scratch (static device globals; no allocation) ----------------
__device__ float g_x   [NODES * HID];
__device__ float g_pq  [NODES * 2 * HID];   // [P | Q] per node
__device__ float g_H   [NODES * HID];
__device__ float g_aggr[NODES * HID];
__device__ float g_t   [NODES * HID];
__device__ int   g_esrc[EDGES];
__device__ float g_eea [EDGES];
__device__ int   g_deg [NODES];
__device__ int   g_tmp [NODES];
__device__ int   g_rowptr[NODES + 1];
__device__ int   g_cursor[NODES];
__device__ float g_invdeg[NODES];
__device__ float g_gate  [NODES];
__device__ float g_wT  [6 * HID * HID];     // 6 transposed weight mats per layer
__device__ float g_gvec[HID];
__device__ int   g_is64;
__device__ int   g_bsum[64];
__device__ int   g_boff[64];

// ================= helpers =================
__device__ __forceinline__ uint32_t cvt_tf32(float x) {
    uint32_t r;
    asm("cvt.rna.tf32.f32 %0, %1;" : "=r"(r) : "f"(x));
    return r;
}
__device__ __forceinline__ void mma8(float* c, const uint32_t* a, const uint32_t* b) {
    asm volatile(
        "mma.sync.aligned.m16n8k8.row.col.f32.tf32.tf32.f32 "
        "{%0,%1,%2,%3},{%4,%5,%6,%7},{%8,%9},{%0,%1,%2,%3};"
        : "+f"(c[0]), "+f"(c[1]), "+f"(c[2]), "+f"(c[3])
        : "r"(a[0]), "r"(a[1]), "r"(a[2]), "r"(a[3]), "r"(b[0]), "r"(b[1]));
}

// ================= CSR build =================
__global__ void k_detect(const int* __restrict__ ei) {
    if (blockIdx.x == 0 && threadIdx.x == 0) {
        int z = 1;
        #pragma unroll
        for (int i = 1; i < 16; i += 2) if (ei[i] != 0) z = 0;
        g_is64 = z;
    }
}
__global__ void k_zero_deg(int N) {
    int i = blockIdx.x * blockDim.x + threadIdx.x;
    if (i < N) g_deg[i] = 0;
}
__global__ void k_count(const int* __restrict__ ei, int E) {
    int e = blockIdx.x * blockDim.x + threadIdx.x;
    if (e >= E) return;
    int is64 = g_is64;
    int dst = is64 ? ei[2 * E + 2 * e] : ei[E + e];
    atomicAdd(&g_deg[dst], 1);
}
__global__ void k_scan1(int N) {
    __shared__ int s[1024];
    int tid = threadIdx.x;
    int i = blockIdx.x * 1024 + tid;
    int v = (i < N) ? g_deg[i] : 0;
    s[tid] = v;
    __syncthreads();
    for (int off = 1; off < 1024; off <<= 1) {
        int t = (tid >= off) ? s[tid - off] : 0;
        __syncthreads();
        s[tid] += t;
        __syncthreads();
    }
    if (i < N) g_tmp[i] = s[tid];
    if (tid == 1023) g_bsum[blockIdx.x] = s[1023];
}
__global__ void k_scan2(int nb) {
    __shared__ int s[64];
    int tid = threadIdx.x;
    int v = (tid < nb) ? g_bsum[tid] : 0;
    s[tid] = v;
    __syncthreads();
    for (int off = 1; off < 64; off <<= 1) {
        int t = (tid >= off) ? s[tid - off] : 0;
        __syncthreads();
        s[tid] += t;
        __syncthreads();
    }
    g_boff[tid] = s[tid] - v;   // exclusive
}
__global__ void k_scan3(int N) {
    int i = blockIdx.x * blockDim.x + threadIdx.x;
    if (i >= N) return;
    int incl = g_tmp[i] + g_boff[i >> 10];
    int d = g_deg[i];
    int excl = incl - d;
    g_rowptr[i] = excl;
    g_cursor[i] = excl;
    g_invdeg[i] = 1.0f / fmaxf((float)d, 1.0f);
    g_gate[i]   = (d > 0) ? 1.0f : 0.0f;
    if (i == N - 1) g_rowptr[N] = incl;
}
__global__ void k_scatter(const int* __restrict__ ei, const float* __restrict__ ea, int E) {
    int e = blockIdx.x * blockDim.x + threadIdx.x;
    if (e >= E) return;
    int is64 = g_is64;
    int src = is64 ? ei[2 * e]         : ei[e];
    int dst = is64 ? ei[2 * E + 2 * e] : ei[E + e];
    int pos = atomicAdd(&g_cursor[dst], 1);
    g_esrc[pos] = src;
    g_eea[pos]  = ea[e];
}

// ================= encoder =================
__global__ void k_encode(const float* __restrict__ nf, const float* __restrict__ W,
                         const float* __restrict__ b, int N) {
    int t = blockIdx.x * blockDim.x + threadIdx.x;
    if (t >= N * HID) return;
    int n = t >> 7, c = t & 127;
    float acc = b[c];
    #pragma unroll
    for (int k = 0; k < 5; k++) acc = fmaf(nf[n * 5 + k], W[k * HID + c], acc);
    g_x[t] = acc;
}

// ================= per-layer weight transpose repack =================
// g_wT[w][j][k] = B^T for 6 GEMM operands: W1a,W1b,W2,U1a,U1b,U2
__global__ void k_repackT(const float* __restrict__ W1, const float* __restrict__ W2,
                          const float* __restrict__ U1, const float* __restrict__ U2) {
    int t = blockIdx.x * blockDim.x + threadIdx.x;   // < 6*16384
    int w = t >> 14;
    int j = (t >> 7) & 127;
    int k = t & 127;
    float v;
    switch (w) {
        case 0:  v = W1[k * 128 + j];          break;
        case 1:  v = W1[(128 + k) * 128 + j];  break;
        case 2:  v = W2[k * 128 + j];          break;
        case 3:  v = U1[k * 128 + j];          break;
        case 4:  v = U1[(128 + k) * 128 + j];  break;
        default: v = U2[k * 128 + j];          break;
    }
    g_wT[t] = v;
}

// ================= tf32 mma.sync GEMM: 128x128 CTA tile, K=128 =================
// 256 threads = 8 warps (2 m x 4 n); warp tile 64x32; mma m16n8k8.
// C[M,NO] = epilogue( A1@B1^T (+ A2@B2^T) )
//   BIAS: +bias[col]        SCALE: C = D*rowscale[m] + rowgate[m]*bias[col]
//   RELU: clamp             LN: relu(LayerNorm(D+bias)*lng+lnb)
#define SM_STRIDE 68
#define GEMM_SMEM_BYTES (2 * 128 * SM_STRIDE * 4)

template<bool DUAL, bool BIAS, bool RELU, bool SCALE, bool LN>
__global__ void __launch_bounds__(256, 2)
gemm_mma(const float* __restrict__ A1, const float* __restrict__ A2,
         const float* __restrict__ B1, const float* __restrict__ B2,
         const float* __restrict__ bias,
         const float* __restrict__ rowscale, const float* __restrict__ rowgate,
         const float* __restrict__ lng, const float* __restrict__ lnb,
         float* __restrict__ C, int M, int NO)
{
    extern __shared__ uint32_t sm[];
    uint32_t* As = sm;                       // [128][68]
    uint32_t* Bs = sm + 128 * SM_STRIDE;     // [128][68]

    const int tid = threadIdx.x;
    const int wid = tid >> 5, lane = tid & 31;
    const int g = lane >> 2, tig = lane & 3;
    const int warp_m = wid >> 2, warp_n = wid & 3;
    const int mw = warp_m * 64, nw = warp_n * 32;
    const int m0 = blockIdx.x * 128;

    float acc[4][4][4];
    #pragma unroll
    for (int i = 0; i < 4; i++)
        #pragma unroll
        for (int j = 0; j < 4; j++)
            #pragma unroll
            for (int r = 0; r < 4; r++) acc[i][j][r] = 0.0f;

    const int npass = DUAL ? 2 : 1;
    for (int p = 0; p < npass; p++) {
        const float* A = (DUAL && p) ? A2 : A1;
        const float* B = (DUAL && p) ? B2 : B1;
        for (int c = 0; c < 2; c++) {
            __syncthreads();    // protect smem from previous chunk's readers
            // ---- fill A,B chunk (64 K-cols), converting to tf32 ----
            #pragma unroll
            for (int u = 0; u < 8; u++) {
                int linear = u * 256 + tid;          // 0..2047
                int row = linear >> 4;
                int q   = linear & 15;
                float4 av = make_float4(0.f, 0.f, 0.f, 0.f);
                if (m0 + row < M)
                    av = *(const float4*)&A[(size_t)(m0 + row) * 128 + c * 64 + q * 4];
                uint4 ap;
                ap.x = cvt_tf32(av.x); ap.y = cvt_tf32(av.y);
                ap.z = cvt_tf32(av.z); ap.w = cvt_tf32(av.w);
                *(uint4*)&As[row * SM_STRIDE + q * 4] = ap;
                float4 bv = *(const float4*)&B[(size_t)row * 128 + c * 64 + q * 4];
                uint4 bp;
                bp.x = cvt_tf32(bv.x); bp.y = cvt_tf32(bv.y);
                bp.z = cvt_tf32(bv.z); bp.w = cvt_tf32(bv.w);
                *(uint4*)&Bs[row * SM_STRIDE + q * 4] = bp;
            }
            __syncthreads();
            // ---- 8 k-steps over this chunk ----
            #pragma unroll
            for (int ks = 0; ks < 8; ks++) {
                const int k0 = ks * 8;
                uint32_t af[4][4], bf[4][2];
                #pragma unroll
                for (int i = 0; i < 4; i++) {
                    const uint32_t* base = &As[(mw + i * 16 + g) * SM_STRIDE + k0 + tig];
                    af[i][0] = base[0];
                    af[i][1] = base[8 * SM_STRIDE];
                    af[i][2] = base[4];
                    af[i][3] = base[8 * SM_STRIDE + 4];
                }
                #pragma unroll
                for (int j = 0; j < 4; j++) {
                    const uint32_t* base = &Bs[(nw + j * 8 + g) * SM_STRIDE + k0 + tig];
                    bf[j][0] = base[0];
                    bf[j][1] = base[4];
                }
                #pragma unroll
                for (int i = 0; i < 4; i++)
                    #pragma unroll
                    for (int j = 0; j < 4; j++)
                        mma8(acc[i][j], af[i], bf[j]);
            }
        }
    }

    // ---------------- epilogue ----------------
    // preload per-thread column params
    float bcol[4][2];
    #pragma unroll
    for (int j = 0; j < 4; j++) {
        int col = nw + j * 8 + 2 * tig;
        bcol[j][0] = BIAS ? bias[col]     : 0.0f;
        bcol[j][1] = BIAS ? bias[col + 1] : 0.0f;
    }

    if constexpr (LN) {
        __syncthreads();                    // done with As/Bs; reuse for reductions
        float* sS  = (float*)sm;            // [128][4]
        float* sS2 = (float*)(sm + 512);    // [128][4]
        float gcol[4][2], lcol[4][2];
        #pragma unroll
        for (int j = 0; j < 4; j++) {
            int col = nw + j * 8 + 2 * tig;
            gcol[j][0] = lng[col];     gcol[j][1] = lng[col + 1];
            lcol[j][0] = lnb[col];     lcol[j][1] = lnb[col + 1];
        }
        #pragma unroll
        for (int i = 0; i < 4; i++) {
            #pragma unroll
            for (int h = 0; h < 2; h++) {
                float s = 0.f, s2 = 0.f;
                #pragma unroll
                for (int j = 0; j < 4; j++) {
                    #pragma unroll
                    for (int r = 0; r < 2; r++) {
                        float v = acc[i][j][2 * h + r] + bcol[j][r];
                        s += v; s2 += v * v;
                    }
                }
                s  += __shfl_xor_sync(0xffffffffu, s, 1);
                s  += __shfl_xor_sync(0xffffffffu, s, 2);
                s2 += __shfl_xor_sync(0xffffffffu, s2, 1);
                s2 += __shfl_xor_sync(0xffffffffu, s2, 2);
                if (tig == 0) {
                    int rl = mw + i * 16 + g + 8 * h;
                    sS [rl * 4 + warp_n] = s;
                    sS2[rl * 4 + warp_n] = s2;
                }
            }
        }
        __syncthreads();
        #pragma unroll
        for (int i = 0; i < 4; i++) {
            #pragma unroll
            for (int h = 0; h < 2; h++) {
                int rl = mw + i * 16 + g + 8 * h;
                int row = m0 + rl;
                float s  = sS [rl * 4] + sS [rl * 4 + 1] + sS [rl * 4 + 2] + sS [rl * 4 + 3];
                float s2 = sS2[rl * 4] + sS2[rl * 4 + 1] + sS2[rl * 4 + 2] + sS2[rl * 4 + 3];
                float mu   = s * (1.0f / 128.0f);
                float var  = s2 * (1.0f / 128.0f) - mu * mu;
                float rstd = rsqrtf(var + 1e-5f);
                if (row < M) {
                    #pragma unroll
                    for (int j = 0; j < 4; j++) {
                        int col = nw + j * 8 + 2 * tig;
                        float2 o;
                        o.x = fmaxf((acc[i][j][2*h]   + bcol[j][0] - mu) * rstd * gcol[j][0] + lcol[j][0], 0.f);
                        o.y = fmaxf((acc[i][j][2*h+1] + bcol[j][1] - mu) * rstd * gcol[j][1] + lcol[j][1], 0.f);
                        *(float2*)&C[(size_t)row * NO + col] = o;
                    }
                }
            }
        }
    } else {
        #pragma unroll
        for (int i = 0; i < 4; i++) {
            #pragma unroll
            for (int h = 0; h < 2; h++) {
                int row = m0 + mw + i * 16 + g + 8 * h;
                if (row >= M) continue;
                float rs = 1.f, gt = 1.f;
                if (SCALE) { rs = rowscale[row]; gt = rowgate[row]; }
                #pragma unroll
                for (int j = 0; j < 4; j++) {
                    int col = nw + j * 8 + 2 * tig;
                    float v0 = acc[i][j][2 * h];
                    float v1 = acc[i][j][2 * h + 1];
                    if (SCALE) {
                        v0 = v0 * rs + gt * bcol[j][0];
                        v1 = v1 * rs + gt * bcol[j][1];
                    } else if (BIAS) {
                        v0 += bcol[j][0];
                        v1 += bcol[j][1];
                    }
                    if (RELU) { v0 = fmaxf(v0, 0.f); v1 = fmaxf(v1, 0.f); }
                    float2 o; o.x = v0; o.y = v1;
                    *(float2*)&C[(size_t)row * NO + col] = o;
                }
            }
        }
    }
}

// ================= edge aggregation: warp per node =================
__global__ void __launch_bounds__(256) k_aggr(const float* __restrict__ w1c, int N) {
    int warp = (blockIdx.x * blockDim.x + threadIdx.x) >> 5;
    int lane = threadIdx.x & 31;
    if (warp >= N) return;
    int node = warp;
    float4 p = *(const float4*)&g_pq[(size_t)node * 256 + lane * 4];
    float4 w = *(const float4*)&w1c[lane * 4];
    float4 acc = make_float4(0.f, 0.f, 0.f, 0.f);
    int s0 = g_rowptr[node], s1 = g_rowptr[node + 1];
    for (int j = s0; j < s1; j++) {
        int src  = g_esrc[j];
        float ea = g_eea[j];
        float4 q = *(const float4*)&g_pq[(size_t)src * 256 + 128 + lane * 4];
        acc.x += fmaxf(fmaf(ea, w.x, p.x + q.x), 0.0f);
        acc.y += fmaxf(fmaf(ea, w.y, p.y + q.y), 0.0f);
        acc.z += fmaxf(fmaf(ea, w.z, p.z + q.z), 0.0f);
        acc.w += fmaxf(fmaf(ea, w.w, p.w + q.w), 0.0f);
    }
    *(float4*)&g_H[(size_t)node * 128 + lane * 4] = acc;
}

// ================= readout =================
__global__ void k_zero_gvec() { if (threadIdx.x < 128) g_gvec[threadIdx.x] = 0.0f; }
__global__ void k_mean(int N) {
    int c = threadIdx.x;
    int rows_per = (N + gridDim.x - 1) / gridDim.x;
    int r0 = blockIdx.x * rows_per;
    int r1 = min(r0 + rows_per, N);
    float s = 0.0f;
    for (int r = r0; r < r1; r++) s += g_x[(size_t)r * 128 + c];
    atomicAdd(&g_gvec[c], s);
}
__global__ void k_out(const float* __restrict__ W1, const float* __restrict__ b1,
                      const float* __restrict__ W2, const float* __restrict__ b2,
                      float* __restrict__ out, float invN) {
    __shared__ float gs[128];
    __shared__ float hs[128];
    int c = threadIdx.x;
    gs[c] = g_gvec[c] * invN;
    __syncthreads();
    float a = b1[c];
    #pragma unroll 8
    for (int k = 0; k < 128; k++) a = fmaf(gs[k], W1[k * 128 + c], a);
    hs[c] = fmaxf(a, 0.0f);
    __syncthreads();
    float o = b2[c];
    #pragma unroll 8
    for (int k = 0; k < 128; k++) o = fmaf(hs[k], W2[k * 128 + c], o);
    out[c] = o;
}

// ================= launch =================
extern "C" void kernel_launch(void* const* d_in, const int* in_sizes, int n_in,
                              void* d_out, int out_size) {
    const float* node_feat = (const float*)d_in[0];
    const float* edge_attr = (const float*)d_in[1];
    const float* enc_W  = (const float*)d_in[2];
    const float* enc_b  = (const float*)d_in[3];
    const float* mlp_W1 = (const float*)d_in[4];
    const float* mlp_b1 = (const float*)d_in[5];
    const float* mlp_W2 = (const float*)d_in[6];
    const float* mlp_b2 = (const float*)d_in[7];
    const float* upd_W1 = (const float*)d_in[8];
    const float* upd_b1 = (const float*)d_in[9];
    const float* upd_W2 = (const float*)d_in[10];
    const float* upd_b2 = (const float*)d_in[11];
    const float* ln_g   = (const float*)d_in[12];
    const float* ln_b   = (const float*)d_in[13];
    const float* out_W1 = (const float*)d_in[14];
    const float* out_b1 = (const float*)d_in[15];
    const float* out_W2 = (const float*)d_in[16];
    const float* out_b2 = (const float*)d_in[17];
    const int*   ei     = (const int*)d_in[18];

    const int N = NODES;
    const int E = EDGES;

    float *px, *ppq, *pH, *paggr, *pt, *pwT, *pinv, *pgate;
    cudaGetSymbolAddress((void**)&px,    g_x);
    cudaGetSymbolAddress((void**)&ppq,   g_pq);
    cudaGetSymbolAddress((void**)&pH,    g_H);
    cudaGetSymbolAddress((void**)&paggr, g_aggr);
    cudaGetSymbolAddress((void**)&pt,    g_t);
    cudaGetSymbolAddress((void**)&pwT,   g_wT);
    cudaGetSymbolAddress((void**)&pinv,  g_invdeg);
    cudaGetSymbolAddress((void**)&pgate, g_gate);

    cudaFuncSetAttribute(gemm_mma<false, true,  false, false, false>,
                         cudaFuncAttributeMaxDynamicSharedMemorySize, GEMM_SMEM_BYTES);
    cudaFuncSetAttribute(gemm_mma<false, false, false, false, false>,
                         cudaFuncAttributeMaxDynamicSharedMemorySize, GEMM_SMEM_BYTES);
    cudaFuncSetAttribute(gemm_mma<false, true,  false, true,  false>,
                         cudaFuncAttributeMaxDynamicSharedMemorySize, GEMM_SMEM_BYTES);
    cudaFuncSetAttribute(gemm_mma<true,  true,  true,  false, false>,
                         cudaFuncAttributeMaxDynamicSharedMemorySize, GEMM_SMEM_BYTES);
    cudaFuncSetAttribute(gemm_mma<false, true,  false, false, true>,
                         cudaFuncAttributeMaxDynamicSharedMemorySize, GEMM_SMEM_BYTES);

    // CSR build
    k_detect<<<1, 32>>>(ei);
    k_zero_deg<<<(N + 255) / 256, 256>>>(N);
    k_count<<<(E + 255) / 256, 256>>>(ei, E);
    k_scan1<<<(N + 1023) / 1024, 1024>>>(N);
    k_scan2<<<1, 64>>>((N + 1023) / 1024);
    k_scan3<<<(N + 255) / 256, 256>>>(N);
    k_scatter<<<(E + 255) / 256, 256>>>(ei, edge_attr, E);

    // encoder
    k_encode<<<(N * HID + 255) / 256, 256>>>(node_feat, enc_W, enc_b, N);

    const int gtiles = (N + 127) / 128;

    for (int l = 0; l < NLAYER; l++) {
        const float* W1l = mlp_W1 + (size_t)l * 257 * 128;
        k_repackT<<<6 * 16384 / 256, 256>>>(W1l, mlp_W2 + (size_t)l * 128 * 128,
                                            upd_W1 + (size_t)l * 256 * 128,
                                            upd_W2 + (size_t)l * 128 * 128);

        // P = x @ W1a^T + b1   (C stride 256, offset 0)
        gemm_mma<false, true, false, false, false><<<gtiles, 256, GEMM_SMEM_BYTES>>>(
            px, nullptr, pwT + 0 * 16384, nullptr, mlp_b1 + l * 128,
            nullptr, nullptr, nullptr, nullptr, ppq, N, 256);

        // Q = x @ W1b^T        (C stride 256, offset 128)
        gemm_mma<false, false, false, false, false><<<gtiles, 256, GEMM_SMEM_BYTES>>>(
            px, nullptr, pwT + 1 * 16384, nullptr, nullptr,
            nullptr, nullptr, nullptr, nullptr, ppq + 128, N, 256);

        // H[n] = sum relu(P[n] + Q[src] + ea*w1c)
        k_aggr<<<(N + 7) / 8, 256>>>(W1l + 256 * 128, N);

        // aggr = (H @ W2^T) * inv_deg + gate * b2
        gemm_mma<false, true, false, true, false><<<gtiles, 256, GEMM_SMEM_BYTES>>>(
            pH, nullptr, pwT + 2 * 16384, nullptr, mlp_b2 + l * 128,
            pinv, pgate, nullptr, nullptr, paggr, N, 128);

        // t = relu(x @ U1a^T + aggr @ U1b^T + b1)
        gemm_mma<true, true, true, false, false><<<gtiles, 256, GEMM_SMEM_BYTES>>>(
            px, paggr, pwT + 3 * 16384, pwT + 4 * 16384, upd_b1 + l * 128,
            nullptr, nullptr, nullptr, nullptr, pt, N, 128);

        // x = relu(LN(t @ U2^T + b2))
        gemm_mma<false, true, false, false, true><<<gtiles, 256, GEMM_SMEM_BYTES>>>(
            pt, nullptr, pwT + 5 * 16384, nullptr, upd_b2 + l * 128,
            nullptr, nullptr, ln_g + l * 128, ln_b + l * 128, px, N, 128);
    }

    // readout
    k_zero_gvec<<<1, 128>>>();
    k_mean<<<400, 128>>>(N);
    k_out<<<1, 128>>>(out_W1, out_b1, out_W2, out_b2, (float*)d_out, 1.0f / (float)N);
}